// round 12
// baseline (speedup 1.0000x reference)
#include <cuda_runtime.h>
#include <cstdint>

#define DIM 128
#define NSLICE 16          // k-slices per batch
#define NTHREADS 256       // 8 warps per block
#define NBATCH 8

// ---------------- tagged dataflow scratch (static __device__, no allocation) ----
// Each element: (tag << 32) | float_bits. Tag = replay_epoch+1. Value+readiness in
// one 8B word -> single relaxed store publishes, single relaxed load consumes.
__device__ unsigned long long g_h2x[NBATCH][5 * DIM];   // rows 2j||2j+1 contiguous
__device__ unsigned long long g_tbx[NBATCH][2 * DIM];
__device__ unsigned long long g_h1x[NBATCH][2 * DIM];   // rows 0||1 contiguous
__device__ unsigned long long g_tb0x[NBATCH][DIM];
__device__ unsigned long long g_epoch;                  // 128 increments per replay

__device__ __forceinline__ float prelu_f(float x, float a) {
    return x >= 0.0f ? x : a * x;
}

// xor-butterfly: full sum in EVERY lane
__device__ __forceinline__ float wred(float v) {
    v += __shfl_xor_sync(0xffffffffu, v, 16);
    v += __shfl_xor_sync(0xffffffffu, v, 8);
    v += __shfl_xor_sync(0xffffffffu, v, 4);
    v += __shfl_xor_sync(0xffffffffu, v, 2);
    v += __shfl_xor_sync(0xffffffffu, v, 1);
    return v;
}

__device__ __forceinline__ void st_tag(unsigned long long* p, float val, unsigned tag) {
    unsigned long long v = ((unsigned long long)tag << 32)
                         | (unsigned long long)__float_as_uint(val);
    asm volatile("st.relaxed.gpu.global.u64 [%0], %1;" :: "l"(p), "l"(v) : "memory");
}

// Warp-collective: active lanes poll 8 tagged words until tag matches; inactive
// lanes just participate in the vote. On success x[0..7] holds the values.
__device__ __forceinline__ void poll8(const unsigned long long* tp, bool active,
                                      unsigned tag, float* x) {
    for (;;) {
        unsigned long long v[8];
        bool ok = true;
        if (active) {
            #pragma unroll
            for (int i = 0; i < 8; i++)
                asm volatile("ld.relaxed.gpu.global.u64 %0, [%1];"
                             : "=l"(v[i]) : "l"(tp + i) : "memory");
            #pragma unroll
            for (int i = 0; i < 8; i++)
                ok &= ((unsigned)(v[i] >> 32) == tag);
        }
        if (__all_sync(0xffffffffu, ok)) {
            if (active) {
                #pragma unroll
                for (int i = 0; i < 8; i++)
                    x[i] = __uint_as_float((unsigned)(v[i] & 0xffffffffu));
            }
            return;
        }
    }
}

// load 8 consecutive smem floats (32B-aligned) into x[8]
__device__ __forceinline__ void ld8s(const float* p, float* x) {
    float4 a = ((const float4*)p)[0];
    float4 b = ((const float4*)p)[1];
    x[0]=a.x; x[1]=a.y; x[2]=a.z; x[3]=a.w;
    x[4]=b.x; x[5]=b.y; x[6]=b.z; x[7]=b.w;
}

__global__ __launch_bounds__(NTHREADS, 1) void encoder_fused_kernel(
    const float* __restrict__ points,  // [B, N3, 3]
    const float* __restrict__ vec2,    // [B, N2, 3]
    const float* __restrict__ vec1,    // [B, N1, 3]
    const float* __restrict__ vec0,    // [B, 1, 3]
    const float* __restrict__ Wp,      // [DIM, 3]
    const float* __restrict__ bp,
    const float* __restrict__ a_leaf,
    const float* __restrict__ Wb2, const float* __restrict__ bb2,
    const float* __restrict__ a2p,
    const float* __restrict__ Wb1, const float* __restrict__ bb1,
    const float* __restrict__ Ws1, const float* __restrict__ bs1,
    const float* __restrict__ a1p,
    const float* __restrict__ Wb0, const float* __restrict__ bb0,
    const float* __restrict__ Ws0, const float* __restrict__ bs0,
    const float* __restrict__ a0p,
    const int* __restrict__ cl2, const int* __restrict__ cr2,
    const int* __restrict__ cl1, const int* __restrict__ cr1,
    const int* __restrict__ cs1,
    const int* __restrict__ cl0, const int* __restrict__ cr0,
    const int* __restrict__ cs0,
    float* __restrict__ out,           // [B, DIM]
    int N3, int N2n, int N1n)
{
    const int b   = blockIdx.x >> 4;
    const int s   = blockIdx.x & (NSLICE - 1);
    const int tid = threadIdx.x;
    const int w   = tid >> 5, l = tid & 31;

    __shared__ int sp[12], sn2[5], sl1[2];
    __shared__ unsigned stag;
    __shared__ __align__(16) float svec2[5][3];
    __shared__ __align__(16) float svec1[2][3];
    __shared__ __align__(16) float svec0[3];
    __shared__ __align__(16) float leaf[12][DIM];  // rows [2j]||[2j+1] contiguous

    // ---- epoch (replay index) + dependency-cone resolution (thread 0) ----
    if (tid == 0) {
        unsigned long long old = atomicAdd(&g_epoch, 1ull);   // issued first; overlaps cone
        int l1a = cl0[0];
        int l1b = cr0[0];
        sl1[0] = l1a; sl1[1] = l1b;
        int n0 = cl1[l1a], n1 = cr1[l1a], n2_ = cl1[l1b], n3 = cr1[l1b], n4 = cs0[0];
        sn2[0] = n0; sn2[1] = n1; sn2[2] = n2_; sn2[3] = n3; sn2[4] = n4;
        sp[0] = cl2[n0];  sp[1] = cr2[n0];
        sp[2] = cl2[n1];  sp[3] = cr2[n1];
        sp[4] = cl2[n2_]; sp[5] = cr2[n2_];
        sp[6] = cl2[n3];  sp[7] = cr2[n3];
        sp[8] = cl2[n4];  sp[9] = cr2[n4];
        sp[10] = cs1[l1a]; sp[11] = cs1[l1b];
        stag = (unsigned)(old / (NBATCH * NSLICE)) + 1u;      // uniform across blocks
    }

    // ---------------- register-preload weight slices, d-contiguous layout ----------------
    const int kB  = (s << 3) + w;           // phase B/E/F channel
    const int idx = (s << 4) + (w << 1);    // phase C/D pair base
    const int jCD = idx >> 7;
    const int k0  = idx & 127, k1 = k0 + 1;

    float wBr[24], wC0r[24], wC1r[24], wEr[24];
    float wD0r[8], wD1r[8], wFr[8];
    {
        const float4* pB  = (const float4*)(Wb2 + (long)kB * 768 + 24 * l);
        const float4* pC0 = (const float4*)(Wb1 + (long)k0 * 768 + 24 * l);
        const float4* pC1 = (const float4*)(Wb1 + (long)k1 * 768 + 24 * l);
        const float4* pE  = (const float4*)(Wb0 + (long)kB * 768 + 24 * l);
        #pragma unroll
        for (int i = 0; i < 6; i++) {
            ((float4*)wBr)[i]  = pB[i];
            ((float4*)wC0r)[i] = pC0[i];
            ((float4*)wC1r)[i] = pC1[i];
            ((float4*)wEr)[i]  = pE[i];
        }
        const float4* pD0 = (const float4*)(Ws1 + (long)k0 * 256 + 8 * l);
        const float4* pD1 = (const float4*)(Ws1 + (long)k1 * 256 + 8 * l);
        const float4* pF  = (const float4*)(Ws0 + (long)kB * 256 + 8 * l);
        ((float4*)wD0r)[0] = pD0[0]; ((float4*)wD0r)[1] = pD0[1];
        ((float4*)wD1r)[0] = pD1[0]; ((float4*)wD1r)[1] = pD1[1];
        ((float4*)wFr)[0]  = pF[0];  ((float4*)wFr)[1]  = pF[1];
    }
    const float bB  = bb2[kB];
    const float bC0 = bb1[k0], bC1 = bb1[k1];
    const float bD0 = bs1[k0], bD1 = bs1[k1];
    const float bE  = bb0[kB], bF = bs0[kB];
    const float AL = a_leaf[0], A2 = a2p[0], A1 = a1p[0], A0 = a0p[0];

    __syncthreads();                       // sp/sl1/sn2/stag visible
    const unsigned tag = stag;

    // ---- preload vec gathers into smem ----
    if (tid < 15) {
        int j = tid / 3, v = tid - 3 * j;
        svec2[j][v] = vec2[((long)b * N2n + sn2[j]) * 3 + v];
    } else if (tid < 21) {
        int t = tid - 15;
        int j = t / 3, v = t - 3 * j;
        svec1[j][v] = vec1[((long)b * N1n + sl1[j]) * 3 + v];
    } else if (tid < 24) {
        svec0[tid - 21] = vec0[(long)b * 3 + (tid - 21)];
    }

    // ---- leaves: 12 rows, h3 = prelu(points @ Wp^T + bp) ----
    for (int i = tid; i < 12 * DIM; i += NTHREADS) {
        int j = i >> 7, k = i & 127;
        const float* pt = points + ((long)b * N3 + sp[j]) * 3;
        float h = fmaf(Wp[k * 3 + 0], pt[0],
                  fmaf(Wp[k * 3 + 1], pt[1],
                  fmaf(Wp[k * 3 + 2], pt[2], bp[k])));
        leaf[j][k] = prelu_f(h, AL);
    }
    __syncthreads();                       // leaf + svec visible to all warps

    // ======== from here on: pure warp-synchronous dataflow, no CTA/grid syncs ========

    // ---- Phase B: layer-2 bilinear, 5 nodes; publish tagged h2 ----
    {
        #pragma unroll
        for (int j = 0; j < 5; j++) {
            float x[8];
            ld8s(&leaf[2 * j][0] + 8 * l, x);
            float a0 = 0.f, a1 = 0.f, a2 = 0.f;
            #pragma unroll
            for (int m = 0; m < 8; m++) {
                a0 = fmaf(x[m], wBr[3 * m + 0], a0);
                a1 = fmaf(x[m], wBr[3 * m + 1], a1);
                a2 = fmaf(x[m], wBr[3 * m + 2], a2);
            }
            float z = a0 * svec2[j][0] + a1 * svec2[j][1] + a2 * svec2[j][2];
            float r = wred(z);
            if (l == 0)
                st_tag(&g_h2x[b][j * DIM + kB], prelu_f(r + bB, A2), tag);
        }
    }

    // ---- Phase C: layer-1 bilinear; poll h2 rows 2jCD..2jCD+1, publish tb ----
    {
        float x[8];
        poll8(&g_h2x[b][2 * jCD * DIM + 8 * l], true, tag, x);
        float a00 = 0.f, a01 = 0.f, a02 = 0.f;
        float a10 = 0.f, a11 = 0.f, a12 = 0.f;
        #pragma unroll
        for (int m = 0; m < 8; m++) {
            a00 = fmaf(x[m], wC0r[3 * m + 0], a00);
            a01 = fmaf(x[m], wC0r[3 * m + 1], a01);
            a02 = fmaf(x[m], wC0r[3 * m + 2], a02);
            a10 = fmaf(x[m], wC1r[3 * m + 0], a10);
            a11 = fmaf(x[m], wC1r[3 * m + 1], a11);
            a12 = fmaf(x[m], wC1r[3 * m + 2], a12);
        }
        float z0 = a00 * svec1[jCD][0] + a01 * svec1[jCD][1] + a02 * svec1[jCD][2];
        float z1 = a10 * svec1[jCD][0] + a11 * svec1[jCD][1] + a12 * svec1[jCD][2];
        float r0 = wred(z0), r1 = wred(z1);
        if (l == 0)      st_tag(&g_tbx[b][jCD * DIM + k0], prelu_f(r0 + bC0, A1), tag);
        else if (l == 1) st_tag(&g_tbx[b][jCD * DIM + k1], prelu_f(r1 + bC1, A1), tag);
    }

    // ---- Phase D: sample-merge linear; lanes 0-15 poll tb, 16-31 read leaf smem ----
    {
        float x[8];
        if (l >= 16) ld8s(&leaf[10 + jCD][0] + 8 * (l - 16), x);
        poll8(&g_tbx[b][jCD * DIM + 8 * l], l < 16, tag, x);
        float a0 = 0.f, a1 = 0.f;
        #pragma unroll
        for (int m = 0; m < 8; m++) {
            a0 = fmaf(x[m], wD0r[m], a0);
            a1 = fmaf(x[m], wD1r[m], a1);
        }
        float r0 = wred(a0), r1 = wred(a1);
        if (l == 0)      st_tag(&g_h1x[b][jCD * DIM + k0], prelu_f(r0 + bD0, A1), tag);
        else if (l == 1) st_tag(&g_h1x[b][jCD * DIM + k1], prelu_f(r1 + bD1, A1), tag);
    }

    // ---- Phase E: root bilinear; poll h1 cat (256 contiguous), publish tb0 ----
    {
        float x[8];
        poll8(&g_h1x[b][8 * l], true, tag, x);
        float a0 = 0.f, a1 = 0.f, a2 = 0.f;
        #pragma unroll
        for (int m = 0; m < 8; m++) {
            a0 = fmaf(x[m], wEr[3 * m + 0], a0);
            a1 = fmaf(x[m], wEr[3 * m + 1], a1);
            a2 = fmaf(x[m], wEr[3 * m + 2], a2);
        }
        float z = a0 * svec0[0] + a1 * svec0[1] + a2 * svec0[2];
        float r = wred(z);
        if (l == 0) st_tag(&g_tb0x[b][kB], prelu_f(r + bE, A0), tag);
    }

    // ---- Phase F: root linear; lanes 0-15 poll tb0, 16-31 poll h2[4] (already set) ----
    {
        float x[8];
        const unsigned long long* tp = (l < 16)
            ? &g_tb0x[b][8 * l]
            : &g_h2x[b][4 * DIM + 8 * (l - 16)];
        poll8(tp, true, tag, x);
        float acc = 0.f;
        #pragma unroll
        for (int m = 0; m < 8; m++) acc = fmaf(x[m], wFr[m], acc);
        float r = wred(acc);
        if (l == 0) out[(long)b * DIM + kB] = prelu_f(r + bF, A0);
    }
}

extern "C" void kernel_launch(void* const* d_in, const int* in_sizes, int n_in,
                              void* d_out, int out_size)
{
    const float* points = (const float*)d_in[0];
    const float* vec2   = (const float*)d_in[1];
    const float* vec1   = (const float*)d_in[2];
    const float* vec0   = (const float*)d_in[3];
    const float* Wp     = (const float*)d_in[4];
    const float* bp     = (const float*)d_in[5];
    const float* a_leaf = (const float*)d_in[6];
    const float* Wb2    = (const float*)d_in[7];
    const float* bb2    = (const float*)d_in[8];
    const float* a2     = (const float*)d_in[9];
    const float* Wb1    = (const float*)d_in[10];
    const float* bb1    = (const float*)d_in[11];
    const float* Ws1    = (const float*)d_in[12];
    const float* bs1    = (const float*)d_in[13];
    const float* a1     = (const float*)d_in[14];
    const float* Wb0    = (const float*)d_in[15];
    const float* bb0    = (const float*)d_in[16];
    const float* Ws0    = (const float*)d_in[17];
    const float* bs0    = (const float*)d_in[18];
    const float* a0     = (const float*)d_in[19];
    const int*   cl2    = (const int*)d_in[20];
    const int*   cr2    = (const int*)d_in[21];
    const int*   cl1    = (const int*)d_in[22];
    const int*   cr1    = (const int*)d_in[23];
    const int*   cs1    = (const int*)d_in[24];
    const int*   cl0    = (const int*)d_in[25];
    const int*   cr0    = (const int*)d_in[26];
    const int*   cs0    = (const int*)d_in[27];

    const int B  = out_size / DIM;          // 8
    const int N3 = in_sizes[0] / (3 * B);   // 131072
    const int N2 = in_sizes[1] / (3 * B);   // 65536
    const int N1 = in_sizes[2] / (3 * B);   // 1024

    encoder_fused_kernel<<<B * NSLICE, NTHREADS>>>(
        points, vec2, vec1, vec0,
        Wp, bp, a_leaf, Wb2, bb2, a2,
        Wb1, bb1, Ws1, bs1, a1,
        Wb0, bb0, Ws0, bs0, a0,
        cl2, cr2, cl1, cr1, cs1, cl0, cr0, cs0,
        (float*)d_out, N3, N2, N1);
}

// round 14
// speedup vs baseline: 2.5817x; 2.5817x over previous
#include <cuda_runtime.h>
#include <cstdint>

#define DIM 128
#define NSLICE 16          // k-slices per batch
#define NTHREADS 256       // 8 warps per block
#define NBATCH 8

// ---------------- global scratch (static __device__, no allocation) ----------------
// Row adjacency is load-bearing: h2[2j]||h2[2j+1] and h1[0]||h1[1] read as
// 256 contiguous floats by d-contiguous lanes.
__device__ float g_h2[NBATCH][5][DIM];
__device__ float g_tb[NBATCH][2][DIM];
__device__ float g_h1[NBATCH][2][DIM];
__device__ float g_tb0[NBATCH][DIM];

// per-(batch,phase) barrier: ONE monotonic counter, own 128B line
struct __align__(128) BarSlot { unsigned c; unsigned pad[31]; };
__device__ BarSlot g_bar[NBATCH * 4];

__device__ __forceinline__ float prelu_f(float x, float a) {
    return x >= 0.0f ? x : a * x;
}

// xor-butterfly: full sum in EVERY lane
__device__ __forceinline__ float wred(float v) {
    v += __shfl_xor_sync(0xffffffffu, v, 16);
    v += __shfl_xor_sync(0xffffffffu, v, 8);
    v += __shfl_xor_sync(0xffffffffu, v, 4);
    v += __shfl_xor_sync(0xffffffffu, v, 2);
    v += __shfl_xor_sync(0xffffffffu, v, 1);
    return v;
}

// barrier: fire-and-forget RED arrival (release), poll single counter (acquire)
// until it reaches the precomputed, replay-safe target.
__device__ __forceinline__ void red_bar(int slot, unsigned target) {
    __syncthreads();
    if (threadIdx.x == 0) {
        unsigned* cp = &g_bar[slot].c;
        asm volatile("red.release.gpu.global.add.u32 [%0], %1;"
                     :: "l"(cp), "r"(1u) : "memory");
        unsigned cur;
        do {
            asm volatile("ld.acquire.gpu.global.u32 %0, [%1];"
                         : "=r"(cur) : "l"(cp) : "memory");
        } while ((int)(cur - target) < 0);
    }
    __syncthreads();
}

// load 8 consecutive floats (32B-aligned) into x[8]
__device__ __forceinline__ void ld8(const float* p, float* x) {
    float4 a = ((const float4*)p)[0];
    float4 b = ((const float4*)p)[1];
    x[0]=a.x; x[1]=a.y; x[2]=a.z; x[3]=a.w;
    x[4]=b.x; x[5]=b.y; x[6]=b.z; x[7]=b.w;
}

__global__ __launch_bounds__(NTHREADS, 1) void encoder_fused_kernel(
    const float* __restrict__ points,  // [B, N3, 3]
    const float* __restrict__ vec2,    // [B, N2, 3]
    const float* __restrict__ vec1,    // [B, N1, 3]
    const float* __restrict__ vec0,    // [B, 1, 3]
    const float* __restrict__ Wp,      // [DIM, 3]
    const float* __restrict__ bp,
    const float* __restrict__ a_leaf,
    const float* __restrict__ Wb2, const float* __restrict__ bb2,
    const float* __restrict__ a2p,
    const float* __restrict__ Wb1, const float* __restrict__ bb1,
    const float* __restrict__ Ws1, const float* __restrict__ bs1,
    const float* __restrict__ a1p,
    const float* __restrict__ Wb0, const float* __restrict__ bb0,
    const float* __restrict__ Ws0, const float* __restrict__ bs0,
    const float* __restrict__ a0p,
    const int* __restrict__ cl2, const int* __restrict__ cr2,
    const int* __restrict__ cl1, const int* __restrict__ cr1,
    const int* __restrict__ cs1,
    const int* __restrict__ cl0, const int* __restrict__ cr0,
    const int* __restrict__ cs0,
    float* __restrict__ out,           // [B, DIM]
    int N3, int N2n, int N1n)
{
    const int b   = blockIdx.x >> 4;
    const int s   = blockIdx.x & (NSLICE - 1);
    const int tid = threadIdx.x;
    const int w   = tid >> 5, l = tid & 31;

    // ---- precompute replay-safe barrier targets (thread 0; overlaps preload) ----
    unsigned tgt0 = 0, tgt1 = 0, tgt2 = 0, tgt3 = 0;
    if (tid == 0) {
        unsigned v;
        asm volatile("ld.acquire.gpu.global.u32 %0, [%1];" : "=r"(v) : "l"(&g_bar[b*4+0].c));
        tgt0 = (v / NSLICE) * NSLICE + NSLICE;
        asm volatile("ld.acquire.gpu.global.u32 %0, [%1];" : "=r"(v) : "l"(&g_bar[b*4+1].c));
        tgt1 = (v / NSLICE) * NSLICE + NSLICE;
        asm volatile("ld.acquire.gpu.global.u32 %0, [%1];" : "=r"(v) : "l"(&g_bar[b*4+2].c));
        tgt2 = (v / NSLICE) * NSLICE + NSLICE;
        asm volatile("ld.acquire.gpu.global.u32 %0, [%1];" : "=r"(v) : "l"(&g_bar[b*4+3].c));
        tgt3 = (v / NSLICE) * NSLICE + NSLICE;
    }

    // ---------------- register-preload weight slices, d-contiguous layout ----------------
    // lane l owns cat-dims d = 8l .. 8l+7. Bilinear rows: 24 raw floats (3 per d).
    const int kB  = (s << 3) + w;           // phase B/E/F channel
    const int idx = (s << 4) + (w << 1);    // phase C/D pair base
    const int jCD = idx >> 7;
    const int k0  = idx & 127, k1 = k0 + 1;

    float wBr[24], wC0r[24], wC1r[24], wEr[24];
    float wD0r[8], wD1r[8], wFr[8];
    {
        const float4* pB  = (const float4*)(Wb2 + (long)kB * 768 + 24 * l);
        const float4* pC0 = (const float4*)(Wb1 + (long)k0 * 768 + 24 * l);
        const float4* pC1 = (const float4*)(Wb1 + (long)k1 * 768 + 24 * l);
        const float4* pE  = (const float4*)(Wb0 + (long)kB * 768 + 24 * l);
        #pragma unroll
        for (int i = 0; i < 6; i++) {
            ((float4*)wBr)[i]  = pB[i];
            ((float4*)wC0r)[i] = pC0[i];
            ((float4*)wC1r)[i] = pC1[i];
            ((float4*)wEr)[i]  = pE[i];
        }
        const float4* pD0 = (const float4*)(Ws1 + (long)k0 * 256 + 8 * l);
        const float4* pD1 = (const float4*)(Ws1 + (long)k1 * 256 + 8 * l);
        const float4* pF  = (const float4*)(Ws0 + (long)kB * 256 + 8 * l);
        ((float4*)wD0r)[0] = pD0[0]; ((float4*)wD0r)[1] = pD0[1];
        ((float4*)wD1r)[0] = pD1[0]; ((float4*)wD1r)[1] = pD1[1];
        ((float4*)wFr)[0]  = pF[0];  ((float4*)wFr)[1]  = pF[1];
    }
    const float bB  = bb2[kB];
    const float bC0 = bb1[k0], bC1 = bb1[k1];
    const float bD0 = bs1[k0], bD1 = bs1[k1];
    const float bE  = bb0[kB], bF = bs0[kB];
    const float AL = a_leaf[0], A2 = a2p[0], A1 = a1p[0], A0 = a0p[0];

    __shared__ int sroot[3];
    __shared__ int scl1[1024], scr1[1024], scs1[1024];   // level-1 tables (12KB)
    __shared__ int sp[12];
    __shared__ __align__(16) float svec2[5][3];
    __shared__ __align__(16) float svec1[2][3];
    __shared__ __align__(16) float svec0[3];
    __shared__ __align__(16) float leaf[12][DIM];  // rows [2j]||[2j+1] contiguous

    const bool bulk = (N1n == 1024);

    // ---- Round 1: root indices (thread 0) PARALLEL WITH level-1 table bulk load ----
    // Plain 4B loads: no alignment assumption on harness int buffers.
    if (tid == 0) {
        sroot[0] = cl0[0]; sroot[1] = cr0[0]; sroot[2] = cs0[0];
    }
    if (bulk) {
        #pragma unroll
        for (int i = 0; i < 4; i++) {
            int j = tid + i * NTHREADS;
            scl1[j] = cl1[j];
            scr1[j] = cr1[j];
            scs1[j] = cs1[j];
        }
    }
    __syncthreads();

    // ---- every thread derives the cone from smem (no serialized chain) ----
    const int l1a = sroot[0], l1b = sroot[1], n4 = sroot[2];
    int n0, n1, n2_, n3;
    if (bulk) {
        n0 = scl1[l1a]; n1 = scr1[l1a]; n2_ = scl1[l1b]; n3 = scr1[l1b];
    } else {
        n0 = cl1[l1a];  n1 = cr1[l1a];  n2_ = cl1[l1b];  n3 = cr1[l1b];
    }

    // ---- Round 2: distributed cl2/cr2 gather + sample leaves + ALL vec gathers ----
    if (tid < 10) {
        int j = tid >> 1;
        int node = (j == 0) ? n0 : (j == 1) ? n1 : (j == 2) ? n2_ : (j == 3) ? n3 : n4;
        sp[tid] = (tid & 1) ? cr2[node] : cl2[node];
    } else if (tid == 10) {
        sp[10] = bulk ? scs1[l1a] : cs1[l1a];
    } else if (tid == 11) {
        sp[11] = bulk ? scs1[l1b] : cs1[l1b];
    } else if (tid >= 32 && tid < 47) {
        int t = tid - 32;
        int j = t / 3, v = t - 3 * j;
        int node = (j == 0) ? n0 : (j == 1) ? n1 : (j == 2) ? n2_ : (j == 3) ? n3 : n4;
        svec2[j][v] = vec2[((long)b * N2n + node) * 3 + v];
    } else if (tid >= 47 && tid < 53) {
        int t = tid - 47;
        int j = t / 3, v = t - 3 * j;
        svec1[j][v] = vec1[((long)b * N1n + (j == 0 ? l1a : l1b)) * 3 + v];
    } else if (tid >= 53 && tid < 56) {
        svec0[tid - 53] = vec0[(long)b * 3 + (tid - 53)];
    }
    __syncthreads();

    // ---- Round 3: leaves: 12 rows, h3 = prelu(points @ Wp^T + bp) ----
    for (int i = tid; i < 12 * DIM; i += NTHREADS) {
        int j = i >> 7, k = i & 127;
        const float* pt = points + ((long)b * N3 + sp[j]) * 3;
        float h = fmaf(Wp[k * 3 + 0], pt[0],
                  fmaf(Wp[k * 3 + 1], pt[1],
                  fmaf(Wp[k * 3 + 2], pt[2], bp[k])));
        leaf[j][k] = prelu_f(h, AL);
    }
    __syncthreads();

    // ---- Phase B: layer-2 bilinear, 5 nodes; x from smem, 3-acc per node ----
    {
        #pragma unroll
        for (int j = 0; j < 5; j++) {
            float x[8];
            ld8(&leaf[2 * j][0] + 8 * l, x);       // 256-cat, contiguous rows
            float a0 = 0.f, a1 = 0.f, a2 = 0.f;
            #pragma unroll
            for (int m = 0; m < 8; m++) {
                a0 = fmaf(x[m], wBr[3 * m + 0], a0);
                a1 = fmaf(x[m], wBr[3 * m + 1], a1);
                a2 = fmaf(x[m], wBr[3 * m + 2], a2);
            }
            float z = a0 * svec2[j][0] + a1 * svec2[j][1] + a2 * svec2[j][2];
            float r = wred(z);
            if (l == 0) g_h2[b][j][kB] = prelu_f(r + bB, A2);
        }
    }
    red_bar(b * 4 + 0, tgt0);

    // ---- Phase C: layer-1 bilinear; x straight from global (L2-hot) ----
    {
        float x[8];
        ld8(&g_h2[b][2 * jCD][0] + 8 * l, x);      // rows 2j||2j+1 contiguous
        float a00 = 0.f, a01 = 0.f, a02 = 0.f;
        float a10 = 0.f, a11 = 0.f, a12 = 0.f;
        #pragma unroll
        for (int m = 0; m < 8; m++) {
            a00 = fmaf(x[m], wC0r[3 * m + 0], a00);
            a01 = fmaf(x[m], wC0r[3 * m + 1], a01);
            a02 = fmaf(x[m], wC0r[3 * m + 2], a02);
            a10 = fmaf(x[m], wC1r[3 * m + 0], a10);
            a11 = fmaf(x[m], wC1r[3 * m + 1], a11);
            a12 = fmaf(x[m], wC1r[3 * m + 2], a12);
        }
        float z0 = a00 * svec1[jCD][0] + a01 * svec1[jCD][1] + a02 * svec1[jCD][2];
        float z1 = a10 * svec1[jCD][0] + a11 * svec1[jCD][1] + a12 * svec1[jCD][2];
        float r0 = wred(z0), r1 = wred(z1);
        if (l == 0)      g_tb[b][jCD][k0] = prelu_f(r0 + bC0, A1);
        else if (l == 1) g_tb[b][jCD][k1] = prelu_f(r1 + bC1, A1);
    }
    red_bar(b * 4 + 1, tgt1);

    // ---- Phase D: sample-merge linear; lanes 0-15 read tb (global), 16-31 leaf (smem) ----
    {
        float x[8];
        if (l < 16) ld8(&g_tb[b][jCD][0] + 8 * l, x);
        else        ld8(&leaf[10 + jCD][0] + 8 * (l - 16), x);
        float a0 = 0.f, a1 = 0.f;
        #pragma unroll
        for (int m = 0; m < 8; m++) {
            a0 = fmaf(x[m], wD0r[m], a0);
            a1 = fmaf(x[m], wD1r[m], a1);
        }
        float r0 = wred(a0), r1 = wred(a1);
        if (l == 0)      g_h1[b][jCD][k0] = prelu_f(r0 + bD0, A1);
        else if (l == 1) g_h1[b][jCD][k1] = prelu_f(r1 + bD1, A1);
    }
    red_bar(b * 4 + 2, tgt2);

    // ---- Phase E: root bilinear; x = h1 cat (contiguous global) ----
    {
        float x[8];
        ld8(&g_h1[b][0][0] + 8 * l, x);
        float a0 = 0.f, a1 = 0.f, a2 = 0.f;
        #pragma unroll
        for (int m = 0; m < 8; m++) {
            a0 = fmaf(x[m], wEr[3 * m + 0], a0);
            a1 = fmaf(x[m], wEr[3 * m + 1], a1);
            a2 = fmaf(x[m], wEr[3 * m + 2], a2);
        }
        float z = a0 * svec0[0] + a1 * svec0[1] + a2 * svec0[2];
        float r = wred(z);
        if (l == 0) g_tb0[b][kB] = prelu_f(r + bE, A0);
    }
    red_bar(b * 4 + 3, tgt3);

    // ---- Phase F: root linear; lanes 0-15 read tb0, 16-31 h2[4] (both L2-hot) ----
    {
        float x[8];
        if (l < 16) ld8(&g_tb0[b][0] + 8 * l, x);
        else        ld8(&g_h2[b][4][0] + 8 * (l - 16), x);
        float acc = 0.f;
        #pragma unroll
        for (int m = 0; m < 8; m++) acc = fmaf(x[m], wFr[m], acc);
        float r = wred(acc);
        if (l == 0) out[(long)b * DIM + kB] = prelu_f(r + bF, A0);
    }
}

extern "C" void kernel_launch(void* const* d_in, const int* in_sizes, int n_in,
                              void* d_out, int out_size)
{
    const float* points = (const float*)d_in[0];
    const float* vec2   = (const float*)d_in[1];
    const float* vec1   = (const float*)d_in[2];
    const float* vec0   = (const float*)d_in[3];
    const float* Wp     = (const float*)d_in[4];
    const float* bp     = (const float*)d_in[5];
    const float* a_leaf = (const float*)d_in[6];
    const float* Wb2    = (const float*)d_in[7];
    const float* bb2    = (const float*)d_in[8];
    const float* a2     = (const float*)d_in[9];
    const float* Wb1    = (const float*)d_in[10];
    const float* bb1    = (const float*)d_in[11];
    const float* Ws1    = (const float*)d_in[12];
    const float* bs1    = (const float*)d_in[13];
    const float* a1     = (const float*)d_in[14];
    const float* Wb0    = (const float*)d_in[15];
    const float* bb0    = (const float*)d_in[16];
    const float* Ws0    = (const float*)d_in[17];
    const float* bs0    = (const float*)d_in[18];
    const float* a0     = (const float*)d_in[19];
    const int*   cl2    = (const int*)d_in[20];
    const int*   cr2    = (const int*)d_in[21];
    const int*   cl1    = (const int*)d_in[22];
    const int*   cr1    = (const int*)d_in[23];
    const int*   cs1    = (const int*)d_in[24];
    const int*   cl0    = (const int*)d_in[25];
    const int*   cr0    = (const int*)d_in[26];
    const int*   cs0    = (const int*)d_in[27];

    const int B  = out_size / DIM;          // 8
    const int N3 = in_sizes[0] / (3 * B);   // 131072
    const int N2 = in_sizes[1] / (3 * B);   // 65536
    const int N1 = in_sizes[2] / (3 * B);   // 1024

    encoder_fused_kernel<<<B * NSLICE, NTHREADS>>>(
        points, vec2, vec1, vec0,
        Wp, bp, a_leaf, Wb2, bb2, a2,
        Wb1, bb1, Ws1, bs1, a1,
        Wb0, bb0, Ws0, bs0, a0,
        cl2, cr2, cl1, cr1, cs1, cl0, cr0, cs0,
        (float*)d_out, N3, N2, N1);
}

// round 15
// speedup vs baseline: 2.5867x; 1.0019x over previous
#include <cuda_runtime.h>
#include <cstdint>

#define DIM 128
#define NSLICE 16          // k-slices per batch
#define NTHREADS 256       // 8 warps per block
#define NBATCH 8

// ---------------- global scratch (static __device__, no allocation) ----------------
// Row adjacency is load-bearing: h2[2j]||h2[2j+1] and h1[0]||h1[1] read as
// 256 contiguous floats by d-contiguous lanes.
__device__ float g_h2[NBATCH][5][DIM];
__device__ float g_tb[NBATCH][2][DIM];
__device__ float g_h1[NBATCH][2][DIM];
__device__ float g_tb0[NBATCH][DIM];

// per-(batch,phase) barrier: ONE monotonic counter, own 128B line
struct __align__(128) BarSlot { unsigned c; unsigned pad[31]; };
__device__ BarSlot g_bar[NBATCH * 4];

__device__ __forceinline__ float prelu_f(float x, float a) {
    return x >= 0.0f ? x : a * x;
}

// xor-butterfly: full sum in EVERY lane
__device__ __forceinline__ float wred(float v) {
    v += __shfl_xor_sync(0xffffffffu, v, 16);
    v += __shfl_xor_sync(0xffffffffu, v, 8);
    v += __shfl_xor_sync(0xffffffffu, v, 4);
    v += __shfl_xor_sync(0xffffffffu, v, 2);
    v += __shfl_xor_sync(0xffffffffu, v, 1);
    return v;
}

__device__ __forceinline__ void bar_arrive(int slot) {
    asm volatile("red.release.gpu.global.add.u32 [%0], %1;"
                 :: "l"(&g_bar[slot].c), "r"(1u) : "memory");
}

__device__ __forceinline__ void bar_poll(int slot, unsigned target) {
    unsigned cur;
    do {
        asm volatile("ld.acquire.gpu.global.u32 %0, [%1];"
                     : "=r"(cur) : "l"(&g_bar[slot].c) : "memory");
    } while ((int)(cur - target) < 0);
}

// load 8 consecutive floats (32B-aligned) into x[8]
__device__ __forceinline__ void ld8(const float* p, float* x) {
    float4 a = ((const float4*)p)[0];
    float4 b = ((const float4*)p)[1];
    x[0]=a.x; x[1]=a.y; x[2]=a.z; x[3]=a.w;
    x[4]=b.x; x[5]=b.y; x[6]=b.z; x[7]=b.w;
}

__global__ __launch_bounds__(NTHREADS, 1) void encoder_fused_kernel(
    const float* __restrict__ points,  // [B, N3, 3]
    const float* __restrict__ vec2,    // [B, N2, 3]
    const float* __restrict__ vec1,    // [B, N1, 3]
    const float* __restrict__ vec0,    // [B, 1, 3]
    const float* __restrict__ Wp,      // [DIM, 3]
    const float* __restrict__ bp,
    const float* __restrict__ a_leaf,
    const float* __restrict__ Wb2, const float* __restrict__ bb2,
    const float* __restrict__ a2p,
    const float* __restrict__ Wb1, const float* __restrict__ bb1,
    const float* __restrict__ Ws1, const float* __restrict__ bs1,
    const float* __restrict__ a1p,
    const float* __restrict__ Wb0, const float* __restrict__ bb0,
    const float* __restrict__ Ws0, const float* __restrict__ bs0,
    const float* __restrict__ a0p,
    const int* __restrict__ cl2, const int* __restrict__ cr2,
    const int* __restrict__ cl1, const int* __restrict__ cr1,
    const int* __restrict__ cs1,
    const int* __restrict__ cl0, const int* __restrict__ cr0,
    const int* __restrict__ cs0,
    float* __restrict__ out,           // [B, DIM]
    int N3, int N2n, int N1n)
{
    const int b   = blockIdx.x >> 4;
    const int s   = blockIdx.x & (NSLICE - 1);
    const int tid = threadIdx.x;
    const int w   = tid >> 5, l = tid & 31;

    // ---- precompute replay-safe barrier targets (thread 0; overlaps preload) ----
    unsigned tgt0 = 0, tgt1 = 0, tgt2 = 0, tgt3 = 0;
    if (tid == 0) {
        unsigned v;
        asm volatile("ld.acquire.gpu.global.u32 %0, [%1];" : "=r"(v) : "l"(&g_bar[b*4+0].c));
        tgt0 = (v / NSLICE) * NSLICE + NSLICE;
        asm volatile("ld.acquire.gpu.global.u32 %0, [%1];" : "=r"(v) : "l"(&g_bar[b*4+1].c));
        tgt1 = (v / NSLICE) * NSLICE + NSLICE;
        asm volatile("ld.acquire.gpu.global.u32 %0, [%1];" : "=r"(v) : "l"(&g_bar[b*4+2].c));
        tgt2 = (v / NSLICE) * NSLICE + NSLICE;
        asm volatile("ld.acquire.gpu.global.u32 %0, [%1];" : "=r"(v) : "l"(&g_bar[b*4+3].c));
        tgt3 = (v / NSLICE) * NSLICE + NSLICE;
    }

    // ---------------- work mapping ----------------
    const int kB  = (s << 3) + w;           // phase B/E/F channel
    const int idx = (s << 4) + (w << 1);    // phase C/D pair base
    const int jCD = idx >> 7;
    const int k0  = idx & 127, k1 = k0 + 1;

    // ---- preload ONLY Phase-B weights up front (everything else deferred) ----
    float wBr[24];
    {
        const float4* pB = (const float4*)(Wb2 + (long)kB * 768 + 24 * l);
        #pragma unroll
        for (int i = 0; i < 6; i++) ((float4*)wBr)[i] = pB[i];
    }
    const float bB  = bb2[kB];
    const float bC0 = bb1[k0], bC1 = bb1[k1];
    const float bD0 = bs1[k0], bD1 = bs1[k1];
    const float bE  = bb0[kB], bF = bs0[kB];
    const float AL = a_leaf[0], A2 = a2p[0], A1 = a1p[0], A0 = a0p[0];

    __shared__ int sroot[3];
    __shared__ int scl1[1024], scr1[1024], scs1[1024];   // level-1 tables (12KB)
    __shared__ int sp[12];
    __shared__ __align__(16) float svec2[5][3];
    __shared__ __align__(16) float svec1[2][3];
    __shared__ __align__(16) float svec0[3];
    __shared__ __align__(16) float leaf[12][DIM];  // rows [2j]||[2j+1] contiguous

    const bool bulk = (N1n == 1024);

    // ---- Round 1: root indices (thread 0) PARALLEL WITH level-1 table bulk load ----
    if (tid == 0) {
        sroot[0] = cl0[0]; sroot[1] = cr0[0]; sroot[2] = cs0[0];
    }
    if (bulk) {
        #pragma unroll
        for (int i = 0; i < 4; i++) {
            int j = tid + i * NTHREADS;
            scl1[j] = cl1[j];
            scr1[j] = cr1[j];
            scs1[j] = cs1[j];
        }
    }
    __syncthreads();

    const int l1a = sroot[0], l1b = sroot[1], n4 = sroot[2];
    int n0, n1, n2_, n3;
    if (bulk) {
        n0 = scl1[l1a]; n1 = scr1[l1a]; n2_ = scl1[l1b]; n3 = scr1[l1b];
    } else {
        n0 = cl1[l1a];  n1 = cr1[l1a];  n2_ = cl1[l1b];  n3 = cr1[l1b];
    }

    // ---- Round 2: distributed cl2/cr2 gather + sample leaves + ALL vec gathers ----
    if (tid < 10) {
        int j = tid >> 1;
        int node = (j == 0) ? n0 : (j == 1) ? n1 : (j == 2) ? n2_ : (j == 3) ? n3 : n4;
        sp[tid] = (tid & 1) ? cr2[node] : cl2[node];
    } else if (tid == 10) {
        sp[10] = bulk ? scs1[l1a] : cs1[l1a];
    } else if (tid == 11) {
        sp[11] = bulk ? scs1[l1b] : cs1[l1b];
    } else if (tid >= 32 && tid < 47) {
        int t = tid - 32;
        int j = t / 3, v = t - 3 * j;
        int node = (j == 0) ? n0 : (j == 1) ? n1 : (j == 2) ? n2_ : (j == 3) ? n3 : n4;
        svec2[j][v] = vec2[((long)b * N2n + node) * 3 + v];
    } else if (tid >= 47 && tid < 53) {
        int t = tid - 47;
        int j = t / 3, v = t - 3 * j;
        svec1[j][v] = vec1[((long)b * N1n + (j == 0 ? l1a : l1b)) * 3 + v];
    } else if (tid >= 53 && tid < 56) {
        svec0[tid - 53] = vec0[(long)b * 3 + (tid - 53)];
    }
    __syncthreads();

    // ---- Round 3: leaves: 12 rows, h3 = prelu(points @ Wp^T + bp) ----
    for (int i = tid; i < 12 * DIM; i += NTHREADS) {
        int j = i >> 7, k = i & 127;
        const float* pt = points + ((long)b * N3 + sp[j]) * 3;
        float h = fmaf(Wp[k * 3 + 0], pt[0],
                  fmaf(Wp[k * 3 + 1], pt[1],
                  fmaf(Wp[k * 3 + 2], pt[2], bp[k])));
        leaf[j][k] = prelu_f(h, AL);
    }
    __syncthreads();

    // ---- Phase B: layer-2 bilinear, 5 nodes; x from smem, 3-acc per node ----
    {
        #pragma unroll
        for (int j = 0; j < 5; j++) {
            float x[8];
            ld8(&leaf[2 * j][0] + 8 * l, x);
            float a0 = 0.f, a1 = 0.f, a2 = 0.f;
            #pragma unroll
            for (int m = 0; m < 8; m++) {
                a0 = fmaf(x[m], wBr[3 * m + 0], a0);
                a1 = fmaf(x[m], wBr[3 * m + 1], a1);
                a2 = fmaf(x[m], wBr[3 * m + 2], a2);
            }
            float z = a0 * svec2[j][0] + a1 * svec2[j][1] + a2 * svec2[j][2];
            float r = wred(z);
            if (l == 0) g_h2[b][j][kB] = prelu_f(r + bB, A2);
        }
    }

    // ---- Barrier 0 (inline): arrive, then load Phase-C weights DURING the wait ----
    float wC0r[24], wC1r[24];
    __syncthreads();                       // orders phase-B stores before arrival
    if (tid == 0) bar_arrive(b * 4 + 0);
    {
        const float4* pC0 = (const float4*)(Wb1 + (long)k0 * 768 + 24 * l);
        const float4* pC1 = (const float4*)(Wb1 + (long)k1 * 768 + 24 * l);
        #pragma unroll
        for (int i = 0; i < 6; i++) {
            ((float4*)wC0r)[i] = pC0[i];
            ((float4*)wC1r)[i] = pC1[i];
        }
    }
    if (tid == 0) bar_poll(b * 4 + 0, tgt0);
    __syncthreads();

    // ---- Phase C: layer-1 bilinear; x straight from global (L2-hot) ----
    {
        float x[8];
        ld8(&g_h2[b][2 * jCD][0] + 8 * l, x);
        float a00 = 0.f, a01 = 0.f, a02 = 0.f;
        float a10 = 0.f, a11 = 0.f, a12 = 0.f;
        #pragma unroll
        for (int m = 0; m < 8; m++) {
            a00 = fmaf(x[m], wC0r[3 * m + 0], a00);
            a01 = fmaf(x[m], wC0r[3 * m + 1], a01);
            a02 = fmaf(x[m], wC0r[3 * m + 2], a02);
            a10 = fmaf(x[m], wC1r[3 * m + 0], a10);
            a11 = fmaf(x[m], wC1r[3 * m + 1], a11);
            a12 = fmaf(x[m], wC1r[3 * m + 2], a12);
        }
        float z0 = a00 * svec1[jCD][0] + a01 * svec1[jCD][1] + a02 * svec1[jCD][2];
        float z1 = a10 * svec1[jCD][0] + a11 * svec1[jCD][1] + a12 * svec1[jCD][2];
        float r0 = wred(z0), r1 = wred(z1);
        if (l == 0)      g_tb[b][jCD][k0] = prelu_f(r0 + bC0, A1);
        else if (l == 1) g_tb[b][jCD][k1] = prelu_f(r1 + bC1, A1);
    }

    // ---- Barrier 1 (inline): arrive, then load Phase-D + Phase-E weights ----
    float wD0r[8], wD1r[8], wEr[24];
    __syncthreads();
    if (tid == 0) bar_arrive(b * 4 + 1);
    {
        const float4* pD0 = (const float4*)(Ws1 + (long)k0 * 256 + 8 * l);
        const float4* pD1 = (const float4*)(Ws1 + (long)k1 * 256 + 8 * l);
        const float4* pE  = (const float4*)(Wb0 + (long)kB * 768 + 24 * l);
        ((float4*)wD0r)[0] = pD0[0]; ((float4*)wD0r)[1] = pD0[1];
        ((float4*)wD1r)[0] = pD1[0]; ((float4*)wD1r)[1] = pD1[1];
        #pragma unroll
        for (int i = 0; i < 6; i++) ((float4*)wEr)[i] = pE[i];
    }
    if (tid == 0) bar_poll(b * 4 + 1, tgt1);
    __syncthreads();

    // ---- Phase D: sample-merge linear; lanes 0-15 read tb (global), 16-31 leaf (smem) ----
    {
        float x[8];
        if (l < 16) ld8(&g_tb[b][jCD][0] + 8 * l, x);
        else        ld8(&leaf[10 + jCD][0] + 8 * (l - 16), x);
        float a0 = 0.f, a1 = 0.f;
        #pragma unroll
        for (int m = 0; m < 8; m++) {
            a0 = fmaf(x[m], wD0r[m], a0);
            a1 = fmaf(x[m], wD1r[m], a1);
        }
        float r0 = wred(a0), r1 = wred(a1);
        if (l == 0)      g_h1[b][jCD][k0] = prelu_f(r0 + bD0, A1);
        else if (l == 1) g_h1[b][jCD][k1] = prelu_f(r1 + bD1, A1);
    }

    // ---- Barrier 2 (inline): arrive, then load Phase-F weights ----
    float wFr[8];
    __syncthreads();
    if (tid == 0) bar_arrive(b * 4 + 2);
    {
        const float4* pF = (const float4*)(Ws0 + (long)kB * 256 + 8 * l);
        ((float4*)wFr)[0] = pF[0]; ((float4*)wFr)[1] = pF[1];
    }
    if (tid == 0) bar_poll(b * 4 + 2, tgt2);
    __syncthreads();

    // ---- Phase E: root bilinear; x = h1 cat (contiguous global) ----
    {
        float x[8];
        ld8(&g_h1[b][0][0] + 8 * l, x);
        float a0 = 0.f, a1 = 0.f, a2 = 0.f;
        #pragma unroll
        for (int m = 0; m < 8; m++) {
            a0 = fmaf(x[m], wEr[3 * m + 0], a0);
            a1 = fmaf(x[m], wEr[3 * m + 1], a1);
            a2 = fmaf(x[m], wEr[3 * m + 2], a2);
        }
        float z = a0 * svec0[0] + a1 * svec0[1] + a2 * svec0[2];
        float r = wred(z);
        if (l == 0) g_tb0[b][kB] = prelu_f(r + bE, A0);
    }

    // ---- Barrier 3 ----
    __syncthreads();
    if (tid == 0) { bar_arrive(b * 4 + 3); bar_poll(b * 4 + 3, tgt3); }
    __syncthreads();

    // ---- Phase F: root linear; lanes 0-15 read tb0, 16-31 h2[4] (both L2-hot) ----
    {
        float x[8];
        if (l < 16) ld8(&g_tb0[b][0] + 8 * l, x);
        else        ld8(&g_h2[b][4][0] + 8 * (l - 16), x);
        float acc = 0.f;
        #pragma unroll
        for (int m = 0; m < 8; m++) acc = fmaf(x[m], wFr[m], acc);
        float r = wred(acc);
        if (l == 0) out[(long)b * DIM + kB] = prelu_f(r + bF, A0);
    }
}

extern "C" void kernel_launch(void* const* d_in, const int* in_sizes, int n_in,
                              void* d_out, int out_size)
{
    const float* points = (const float*)d_in[0];
    const float* vec2   = (const float*)d_in[1];
    const float* vec1   = (const float*)d_in[2];
    const float* vec0   = (const float*)d_in[3];
    const float* Wp     = (const float*)d_in[4];
    const float* bp     = (const float*)d_in[5];
    const float* a_leaf = (const float*)d_in[6];
    const float* Wb2    = (const float*)d_in[7];
    const float* bb2    = (const float*)d_in[8];
    const float* a2     = (const float*)d_in[9];
    const float* Wb1    = (const float*)d_in[10];
    const float* bb1    = (const float*)d_in[11];
    const float* Ws1    = (const float*)d_in[12];
    const float* bs1    = (const float*)d_in[13];
    const float* a1     = (const float*)d_in[14];
    const float* Wb0    = (const float*)d_in[15];
    const float* bb0    = (const float*)d_in[16];
    const float* Ws0    = (const float*)d_in[17];
    const float* bs0    = (const float*)d_in[18];
    const float* a0     = (const float*)d_in[19];
    const int*   cl2    = (const int*)d_in[20];
    const int*   cr2    = (const int*)d_in[21];
    const int*   cl1    = (const int*)d_in[22];
    const int*   cr1    = (const int*)d_in[23];
    const int*   cs1    = (const int*)d_in[24];
    const int*   cl0    = (const int*)d_in[25];
    const int*   cr0    = (const int*)d_in[26];
    const int*   cs0    = (const int*)d_in[27];

    const int B  = out_size / DIM;          // 8
    const int N3 = in_sizes[0] / (3 * B);   // 131072
    const int N2 = in_sizes[1] / (3 * B);   // 65536
    const int N1 = in_sizes[2] / (3 * B);   // 1024

    encoder_fused_kernel<<<B * NSLICE, NTHREADS>>>(
        points, vec2, vec1, vec0,
        Wp, bp, a_leaf, Wb2, bb2, a2,
        Wb1, bb1, Ws1, bs1, a1,
        Wb0, bb0, Ws0, bs0, a0,
        cl2, cr2, cl1, cr1, cs1, cl0, cr0, cs0,
        (float*)d_out, N3, N2, N1);
}